// round 2
// baseline (speedup 1.0000x reference)
#include <cuda_runtime.h>

// ---------------------------------------------------------------------------
// ASDHead fused: out[b,t,n] = sum_h relu(fproj[b,t,h] + sproj[b,n,h])*w[h] + b0
// One fused kernel per 64-t tile: register GEMM (f32x2 k-pair packed) ->
// skewed shared f-tile -> relu-dot with register-resident s/w + shfl reduce.
// ---------------------------------------------------------------------------

#define D_MODEL 256
#define D_HID   128
#define BATCH   8
#define SEQ     1024
#define NSLOT   64

typedef unsigned long long u64;

__device__ float g_sproj[BATCH * NSLOT * D_HID];  // 256 KB
__device__ float g_Wt[D_HID * D_MODEL];           // W_f^T [h][k], 128 KB

// -------------------- f32x2 helpers ----------------------------------------
__device__ __forceinline__ u64 fma2(u64 a, u64 b, u64 c) {
    u64 d;
    asm("fma.rn.f32x2 %0, %1, %2, %3;" : "=l"(d) : "l"(a), "l"(b), "l"(c));
    return d;
}
__device__ __forceinline__ u64 add2(u64 a, u64 b) {
    u64 d;
    asm("add.rn.f32x2 %0, %1, %2;" : "=l"(d) : "l"(a), "l"(b));
    return d;
}
__device__ __forceinline__ u64 pack2(float lo, float hi) {
    u64 r;
    asm("mov.b64 %0, {%1, %2};" : "=l"(r) : "f"(lo), "f"(hi));
    return r;
}
__device__ __forceinline__ void unpack2(u64 v, float& lo, float& hi) {
    asm("mov.b64 {%0, %1}, %2;" : "=f"(lo), "=f"(hi) : "l"(v));
}

union F4U2 {
    float4 f4;
    struct { u64 a, b; } u;
};

// -------------------- K0: tiled transpose W_f -> g_Wt ----------------------
// grid (8,4), block 256.  g_Wt[h][k] = W_proj[k][h].
__global__ void __launch_bounds__(256) k_transpose(const float* __restrict__ Wproj) {
    __shared__ float tile[32][33];
    int k0 = blockIdx.x * 32, h0 = blockIdx.y * 32;
    int r = threadIdx.x >> 5, c = threadIdx.x & 31;
#pragma unroll
    for (int i = 0; i < 4; i++) {
        int row = i * 8 + r;
        tile[row][c] = Wproj[(k0 + row) * D_HID + h0 + c];
    }
    __syncthreads();
#pragma unroll
    for (int i = 0; i < 4; i++) {
        int row = i * 8 + r;
        g_Wt[(h0 + row) * D_MODEL + k0 + c] = tile[c][row];
    }
}

// -------------------- K1: s_proj (L2-friendly: 64 blocks) ------------------
// grid 64 (b = blk/8, ngroup = blk%8), block 256: warp = n_local, lanes = h-quads.
__global__ void __launch_bounds__(256) k_sproj(const float* __restrict__ slots,
                                               const float* __restrict__ Wproj,
                                               const float* __restrict__ bproj) {
    __shared__ float ssh[8][D_MODEL];
    int b = blockIdx.x >> 3, ng = blockIdx.x & 7;
    int tid = threadIdx.x;
#pragma unroll
    for (int i = 0; i < 2; i++) {
        int q = i * 256 + tid;
        int row = q >> 6, c4 = q & 63;
        *(float4*)&ssh[row][c4 * 4] =
            *(const float4*)(slots + (b * NSLOT + ng * 8 + row) * D_MODEL + c4 * 4);
    }
    __syncthreads();
    int nl = tid >> 5, hq = tid & 31;
    const float* Ws = Wproj + D_MODEL * D_HID;
    float a0 = 0.f, a1 = 0.f, a2 = 0.f, a3 = 0.f;
#pragma unroll 8
    for (int k = 0; k < D_MODEL; k++) {
        float sv = ssh[nl][k];
        float4 wv = *(const float4*)(Ws + k * D_HID + hq * 4);
        a0 = fmaf(sv, wv.x, a0);
        a1 = fmaf(sv, wv.y, a1);
        a2 = fmaf(sv, wv.z, a2);
        a3 = fmaf(sv, wv.w, a3);
    }
    float4 bp = *(const float4*)(bproj + hq * 4);
    float4 o;
    o.x = a0 + bp.x; o.y = a1 + bp.y; o.z = a2 + bp.z; o.w = a3 + bp.w;
    *(float4*)(g_sproj + (b * NSLOT + ng * 8 + nl) * D_HID + hq * 4) = o;
}

// -------------------- K2: fused GEMM + relu-dot ----------------------------
// grid 128 (b = blk/16, t0 = (blk%16)*64), block 256 threads.
// Phase A: C[64,128] = features_tile @ W_f via f32x2 (k-pair packed).
//   warp w owns rows 8w..8w+7, lane l owns cols {l, l+32, l+64, l+96}.
// Phase B: f-tile in skewed shared (chunk stride 36 words, conflict-free),
//   thread = (n = tid>>2, chunk = tid&3 owning 32 h), shfl reduce over 4 lanes.
#define AS_STRIDE 36
#define FS_STRIDE 144   // 4 chunks * 36
#define SMEM_FLOATS (64 * AS_STRIDE + 128 * AS_STRIDE + 64 * FS_STRIDE)

__global__ void __launch_bounds__(256) k_fused(const float* __restrict__ features,
                                               const float* __restrict__ whead,
                                               const float* __restrict__ bhead,
                                               float* __restrict__ out) {
    extern __shared__ float sm[];
    float* As  = sm;                                   // 64 x 36
    float* Bs  = sm + 64 * AS_STRIDE;                  // 128 x 36
    float* fsh = sm + 64 * AS_STRIDE + 128 * AS_STRIDE;  // 64 x 144 (skewed)

    int tid = threadIdx.x, warp = tid >> 5, lane = tid & 31;
    int b = blockIdx.x >> 4, t0 = (blockIdx.x & 15) * 64;
    const float* A = features + (b * SEQ + t0) * D_MODEL;

    u64 acc[8][4];
#pragma unroll
    for (int i = 0; i < 8; i++)
#pragma unroll
        for (int j = 0; j < 4; j++) acc[i][j] = 0ULL;

    // ---------------- Phase A: GEMM -------------------------------------
#pragma unroll 1
    for (int kc = 0; kc < D_MODEL; kc += 32) {
#pragma unroll
        for (int i = 0; i < 2; i++) {   // A tile: 512 float4
            int q = i * 256 + tid;
            int row = q >> 3, c4 = (q & 7) * 4;
            *(float4*)&As[row * AS_STRIDE + c4] =
                *(const float4*)(A + row * D_MODEL + kc + c4);
        }
#pragma unroll
        for (int i = 0; i < 4; i++) {   // B tile: 1024 float4 (g_Wt k-contig)
            int q = i * 256 + tid;
            int row = q >> 3, c4 = (q & 7) * 4;
            *(float4*)&Bs[row * AS_STRIDE + c4] =
                *(const float4*)(g_Wt + row * D_MODEL + kc + c4);
        }
        __syncthreads();

#pragma unroll
        for (int k4 = 0; k4 < 32; k4 += 4) {
            u64 a2[8][2], b2[4][2];
#pragma unroll
            for (int i = 0; i < 8; i++) {
                F4U2 t;
                t.f4 = *(const float4*)&As[(warp * 8 + i) * AS_STRIDE + k4];
                a2[i][0] = t.u.a; a2[i][1] = t.u.b;
            }
#pragma unroll
            for (int j = 0; j < 4; j++) {
                F4U2 t;
                t.f4 = *(const float4*)&Bs[(lane + 32 * j) * AS_STRIDE + k4];
                b2[j][0] = t.u.a; b2[j][1] = t.u.b;
            }
#pragma unroll
            for (int i = 0; i < 8; i++)
#pragma unroll
                for (int j = 0; j < 4; j++) {
                    acc[i][j] = fma2(a2[i][0], b2[j][0], acc[i][j]);
                    acc[i][j] = fma2(a2[i][1], b2[j][1], acc[i][j]);
                }
        }
        __syncthreads();
    }

    // ---------------- writeback f-tile to skewed shared ------------------
    // col n = lane + 32j  ->  skewed col = 36j + lane  (conflict-free STS)
#pragma unroll
    for (int i = 0; i < 8; i++)
#pragma unroll
        for (int j = 0; j < 4; j++) {
            float lo, hi;
            unpack2(acc[i][j], lo, hi);
            fsh[(warp * 8 + i) * FS_STRIDE + 36 * j + lane] = lo + hi;
        }

    // load s/w chunks into registers while fsh settles
    int n = tid >> 2, chunk = tid & 3;
    u64 s2[16], w2[16];
    {
        const float* sp = g_sproj + (b * NSLOT + n) * D_HID + chunk * 32;
        const float* wp = whead + chunk * 32;
#pragma unroll
        for (int i = 0; i < 8; i++) {
            F4U2 t;
            t.f4 = *(const float4*)(sp + i * 4);
            s2[2 * i] = t.u.a; s2[2 * i + 1] = t.u.b;
            t.f4 = *(const float4*)(wp + i * 4);
            w2[2 * i] = t.u.a; w2[2 * i + 1] = t.u.b;
        }
    }
    float bh = bhead[0];
    __syncthreads();

    // ---------------- Phase B: relu-dot ----------------------------------
#pragma unroll 1
    for (int t = 0; t < 64; t++) {
        const float* fp = fsh + t * FS_STRIDE + chunk * 36;
        u64 f2[16];
#pragma unroll
        for (int i = 0; i < 8; i++) {
            F4U2 v;
            v.f4 = *(const float4*)(fp + i * 4);
            f2[2 * i] = v.u.a; f2[2 * i + 1] = v.u.b;
        }
        u64 acc0 = 0ULL, acc1 = 0ULL;
#pragma unroll
        for (int kk = 0; kk < 16; kk++) {
            u64 x = add2(f2[kk], s2[kk]);
            float lo, hi;
            unpack2(x, lo, hi);
            lo = fmaxf(lo, 0.f);   // FMNMX on alu pipe, overlaps fma pipe
            hi = fmaxf(hi, 0.f);
            if (kk & 1) acc1 = fma2(pack2(lo, hi), w2[kk], acc1);
            else        acc0 = fma2(pack2(lo, hi), w2[kk], acc0);
        }
        u64 r = add2(acc0, acc1);
        r = add2(r, __shfl_xor_sync(0xffffffffu, r, 1));
        r = add2(r, __shfl_xor_sync(0xffffffffu, r, 2));
        if (chunk == 0) {
            float lo, hi;
            unpack2(r, lo, hi);
            out[(b * SEQ + t0 + t) * NSLOT + n] = lo + hi + bh;
        }
    }
}

// -------------------- launch -----------------------------------------------
extern "C" void kernel_launch(void* const* d_in, const int* in_sizes, int n_in,
                              void* d_out, int out_size) {
    const float* features = (const float*)d_in[0];  // (8,1024,256)
    const float* slots    = (const float*)d_in[1];  // (8,64,256)
    const float* W_proj   = (const float*)d_in[2];  // (512,128)
    const float* b_proj   = (const float*)d_in[3];  // (128)
    const float* w_head   = (const float*)d_in[4];  // (128)
    const float* b_head   = (const float*)d_in[5];  // (1)
    float* out = (float*)d_out;                     // (8,1024,64)

    static_assert(SMEM_FLOATS * 4 == 64512, "smem layout");
    cudaFuncSetAttribute(k_fused, cudaFuncAttributeMaxDynamicSharedMemorySize,
                         SMEM_FLOATS * 4);

    k_transpose<<<dim3(8, 4), 256>>>(W_proj);
    k_sproj<<<64, 256>>>(slots, W_proj, b_proj);
    k_fused<<<128, 256, SMEM_FLOATS * 4>>>(features, w_head, b_head, out);
}